// round 5
// baseline (speedup 1.0000x reference)
#include <cuda_runtime.h>

// CharRNN on GB300.
//  - prep kernel: EWe = embedding @ W_e  (33x200, replaces the full input GEMM)
//  - rnn kernel: 128 CTAs x 400 threads, 2 batch rows per CTA (one wave, 148 SMs).
//    W_h in registers (50 packed f32x2 pairs/thread, K split in halves).
//    Per step: matvec via fma.rn.f32x2 (K-paired so h pairs come straight from
//    LDS.128), tanh, and FUSED logits (h @ W_o) for the previous step's h.
//  - x is int32 (JAX downcasts int64 without x64 mode — int64 read caused R4's
//    illegal access).

#define H     200
#define NROW  2
#define SEQ   1024
#define VOCAB 33
#define BATCH 256

__device__ float g_EWe[VOCAB * H];

union U64 {
    unsigned long long u;
    float2 f;
};

__device__ __forceinline__ void ffma2(U64 &acc, U64 a, U64 b) {
    asm("fma.rn.f32x2 %0, %1, %2, %0;" : "+l"(acc.u) : "l"(a.u), "l"(b.u));
}

// EWe[v][j] = sum_e emb[v][e] * We[e][j].  33 blocks x 200 threads, tiny.
__global__ void prep_kernel(const float* __restrict__ emb,
                            const float* __restrict__ We) {
    int v = blockIdx.x;
    int j = threadIdx.x;
    float acc = 0.f;
    #pragma unroll 4
    for (int e = 0; e < H; e++)
        acc = fmaf(emb[v * H + e], We[e * H + j], acc);
    g_EWe[v * H + j] = acc;
}

__global__ void __launch_bounds__(400, 1) rnn_kernel(
    const int* __restrict__ x, const float* __restrict__ h0,
    const float* __restrict__ Wh, const float* __restrict__ Wo,
    float* __restrict__ out, int out_elems)
{
    __shared__ float  hbuf[2][NROW][H];        // double-buffered hidden state
    __shared__ float  pmat[NROW][2][H];        // matvec partials (2 K-halves)
    __shared__ float  lpart[NROW][VOCAB][4];   // logits partials (4 K-quarters)
    __shared__ int    tok[NROW][SEQ];          // tokens for this CTA's 2 rows
    __shared__ float2 WoT[VOCAB][H / 2];       // W_o transposed, K-paired

    const int tid = threadIdx.x;
    const int b0  = blockIdx.x * NROW;

    // ---- preload tokens / W_o / initial hidden ----
    for (int idx = tid; idx < NROW * SEQ; idx += 400) {
        int r = idx >> 10, t = idx & (SEQ - 1);
        tok[r][t] = x[(b0 + r) * SEQ + t];
    }
    for (int idx = tid; idx < VOCAB * (H / 2); idx += 400) {
        int v = idx / (H / 2), m = idx % (H / 2);
        WoT[v][m] = make_float2(Wo[(2 * m) * VOCAB + v],
                                Wo[(2 * m + 1) * VOCAB + v]);
    }
    if (tid < NROW * H) {
        int r = tid / H, jj = tid - r * H;
        hbuf[0][r][jj] = h0[(b0 + r) * H + jj];
    }

    // ---- matvec role: thread (q, j), q = K-half, j = output column ----
    const int q = tid / H;         // 0 or 1; doubles as row index in phase 2
    const int j = tid - q * H;     // 0..199

    // W_h column j, K-half q, packed as 50 f32x2 pairs -> registers.
    U64 w[50];
    #pragma unroll
    for (int m = 0; m < 50; m++) {
        int i0 = q * 100 + 2 * m;
        w[m].f.x = Wh[i0 * H + j];
        w[m].f.y = Wh[(i0 + 1) * H + j];
    }

    // ---- logits role: thread (lr, lv, lq): row, vocab, K-quarter ----
    const bool do_log = (tid < NROW * VOCAB * 4);   // 264 threads
    const int  lr = tid / (VOCAB * 4);
    const int  lv = (tid % (VOCAB * 4)) >> 2;
    const int  lq = tid & 3;

    __syncthreads();

    int cur = 0;
    for (int t = 0; t < SEQ; t++) {
        // ================= phase 1: FMA-heavy =================
        // prefetch xw for phase 2 (L1-resident 26KB table, broadcast per row)
        float xw = g_EWe[tok[q][t] * H + j];

        // matvec partials: contribution of K-half q to y[row][j]
        const float4* hr0 = (const float4*)&hbuf[cur][0][q * 100];
        const float4* hr1 = (const float4*)&hbuf[cur][1][q * 100];
        U64 aA, aB, bA, bB;
        aA.u = aB.u = bA.u = bB.u = 0ull;
        #pragma unroll
        for (int m4 = 0; m4 < 25; m4++) {
            float4 v0 = hr0[m4];    // broadcast LDS.128, conflict-free
            float4 v1 = hr1[m4];
            U64 p0, p1, p2, p3;
            p0.f = make_float2(v0.x, v0.y);
            p1.f = make_float2(v0.z, v0.w);
            p2.f = make_float2(v1.x, v1.y);
            p3.f = make_float2(v1.z, v1.w);
            ffma2(aA, p0, w[2 * m4]);
            ffma2(aB, p1, w[2 * m4 + 1]);
            ffma2(bA, p2, w[2 * m4]);
            ffma2(bB, p3, w[2 * m4 + 1]);
        }
        pmat[0][q][j] = aA.f.x + aA.f.y + aB.f.x + aB.f.y;
        pmat[1][q][j] = bA.f.x + bA.f.y + bB.f.x + bB.f.y;

        // fused logits for the PREVIOUS step's h (same hbuf[cur] the matvec reads)
        if (do_log && t > 0) {
            U64 la, lb; la.u = lb.u = 0ull;
            const float2* hl = (const float2*)&hbuf[cur][lr][lq * 50];
            #pragma unroll
            for (int m = 0; m < 25; m++) {
                U64 hv; hv.f = hl[m];
                U64 wv; wv.f = WoT[lv][lq * 25 + m];
                if (m & 1) ffma2(lb, hv, wv); else ffma2(la, hv, wv);
            }
            lpart[lr][lv][lq] = la.f.x + la.f.y + lb.f.x + lb.f.y;
        }
        __syncthreads();

        // ================= phase 2: reduce + tanh + stores =================
        int nxt = cur ^ 1;
        float y = pmat[q][0][j] + pmat[q][1][j];
        hbuf[nxt][q][j] = tanhf(xw + y);

        if (t > 0 && tid < NROW * VOCAB) {
            int r = tid / VOCAB, v = tid - r * VOCAB;
            float L = lpart[r][v][0] + lpart[r][v][1]
                    + lpart[r][v][2] + lpart[r][v][3];
            out[((long long)(b0 + r) * SEQ + (t - 1)) * VOCAB + v] = L;
        }
        __syncthreads();
        cur = nxt;
    }

    // ---- epilogue: logits for the final step (t = SEQ-1) ----
    if (do_log) {
        U64 la, lb; la.u = lb.u = 0ull;
        const float2* hl = (const float2*)&hbuf[cur][lr][lq * 50];
        #pragma unroll
        for (int m = 0; m < 25; m++) {
            U64 hv; hv.f = hl[m];
            U64 wv; wv.f = WoT[lv][lq * 25 + m];
            if (m & 1) ffma2(lb, hv, wv); else ffma2(la, hv, wv);
        }
        lpart[lr][lv][lq] = la.f.x + la.f.y + lb.f.x + lb.f.y;
    }
    __syncthreads();
    if (tid < NROW * VOCAB) {
        int r = tid / VOCAB, v = tid - r * VOCAB;
        float L = lpart[r][v][0] + lpart[r][v][1]
                + lpart[r][v][2] + lpart[r][v][3];
        out[((long long)(b0 + r) * SEQ + (SEQ - 1)) * VOCAB + v] = L;
    }

    // ---- final hidden (second output, if present in d_out) ----
    long long base = (long long)BATCH * SEQ * VOCAB;
    if ((long long)out_elems >= base + (long long)BATCH * H && tid < NROW * H) {
        int r = tid / H, jj = tid - r * H;
        out[base + (long long)(b0 + r) * H + jj] = hbuf[cur][r][jj];
    }
}

extern "C" void kernel_launch(void* const* d_in, const int* in_sizes, int n_in,
                              void* d_out, int out_size) {
    // metadata order: x(int32 — JAX downcast), hidden, embedding, W_e, W_h, W_o
    const int*   x      = (const int*)d_in[0];
    const float* hidden = (const float*)d_in[1];
    const float* emb    = (const float*)d_in[2];
    const float* We     = (const float*)d_in[3];
    const float* Wh     = (const float*)d_in[4];
    const float* Wo     = (const float*)d_in[5];
    float* out = (float*)d_out;

    prep_kernel<<<VOCAB, H>>>(emb, We);
    rnn_kernel<<<BATCH / NROW, 400>>>(x, hidden, Wh, Wo, out, out_size);
}